// round 4
// baseline (speedup 1.0000x reference)
#include <cuda_runtime.h>

#define HH 512
#define WW 512
#define OW 506
#define BATCH 32
#define CH 3
#define TX 64
#define TY 64
#define ITY 70          // TY + 6
#define STRIDE 72       // floats per hs row (even -> 8B-aligned LDS.64)
#define NBLOCKS (8 * 8 * BATCH * CH)

#define F8 0xFFFFFFFFu
__device__ unsigned g_minBits[BATCH] = {
    F8, F8, F8, F8, F8, F8, F8, F8, F8, F8, F8, F8, F8, F8, F8, F8,
    F8, F8, F8, F8, F8, F8, F8, F8, F8, F8, F8, F8, F8, F8, F8, F8};
__device__ unsigned g_maxBits[BATCH];  // zero-init at load
__device__ double g_acc;               // zero-init at load
__device__ unsigned g_done;            // zero-init at load

// ---------------- packed f32x2 helpers ----------------
typedef unsigned long long ull;
__device__ __forceinline__ ull rep2(float f) {
    ull r; asm("mov.b64 %0,{%1,%1};" : "=l"(r) : "f"(f)); return r;
}
__device__ __forceinline__ ull add2(ull a, ull b) {
    ull d; asm("add.rn.f32x2 %0,%1,%2;" : "=l"(d) : "l"(a), "l"(b)); return d;
}
__device__ __forceinline__ ull mul2(ull a, ull b) {
    ull d; asm("mul.rn.f32x2 %0,%1,%2;" : "=l"(d) : "l"(a), "l"(b)); return d;
}
__device__ __forceinline__ ull fma2(ull a, ull b, ull c) {
    ull d; asm("fma.rn.f32x2 %0,%1,%2,%3;" : "=l"(d) : "l"(a), "l"(b), "l"(c)); return d;
}
__device__ __forceinline__ void unpk(ull v, float& a, float& b) {
    asm("mov.b64 {%0,%1},%2;" : "=f"(a), "=f"(b) : "l"(v));
}
__device__ __forceinline__ ull lds2(unsigned a) {
    ull v; asm volatile("ld.shared.b64 %0,[%1];" : "=l"(v) : "r"(a)); return v;
}

// Per-image min/max of img2 (values >= 0 -> uint ordering == float ordering).
__global__ void minmax_kernel(const float* __restrict__ img2) {
    int b = blockIdx.x;
    const float4* p = (const float4*)(img2 + (size_t)b * (CH * HH * WW));
    const int n4 = CH * HH * WW / 4;           // 196608
    const int stride = gridDim.y * blockDim.x; // 8192
    unsigned lo0 = F8, hi0 = 0u, lo1 = F8, hi1 = 0u;
    int i = blockIdx.y * blockDim.x + threadIdx.x;
    for (; i + stride < n4; i += 2 * stride) {
        float4 v = p[i];
        float4 w = p[i + stride];
        unsigned a0 = __float_as_uint(v.x), a1 = __float_as_uint(v.y);
        unsigned a2 = __float_as_uint(v.z), a3 = __float_as_uint(v.w);
        unsigned b0 = __float_as_uint(w.x), b1 = __float_as_uint(w.y);
        unsigned b2 = __float_as_uint(w.z), b3 = __float_as_uint(w.w);
        lo0 = min(lo0, min(min(a0, a1), min(a2, a3)));
        hi0 = max(hi0, max(max(a0, a1), max(a2, a3)));
        lo1 = min(lo1, min(min(b0, b1), min(b2, b3)));
        hi1 = max(hi1, max(max(b0, b1), max(b2, b3)));
    }
    if (i < n4) {
        float4 v = p[i];
        unsigned a0 = __float_as_uint(v.x), a1 = __float_as_uint(v.y);
        unsigned a2 = __float_as_uint(v.z), a3 = __float_as_uint(v.w);
        lo0 = min(lo0, min(min(a0, a1), min(a2, a3)));
        hi0 = max(hi0, max(max(a0, a1), max(a2, a3)));
    }
    unsigned lo = min(lo0, lo1), hi = max(hi0, hi1);
    #pragma unroll
    for (int o = 16; o; o >>= 1) {
        lo = min(lo, __shfl_down_sync(F8, lo, o));
        hi = max(hi, __shfl_down_sync(F8, hi, o));
    }
    __shared__ unsigned slo[8], shi[8];
    int lane = threadIdx.x & 31, w = threadIdx.x >> 5;
    if (lane == 0) { slo[w] = lo; shi[w] = hi; }
    __syncthreads();
    if (threadIdx.x == 0) {
        #pragma unroll
        for (int k = 1; k < 8; k++) { lo = min(lo, slo[k]); hi = max(hi, shi[k]); }
        atomicMin(&g_minBits[b], lo);
        atomicMax(&g_maxBits[b], hi);
    }
}

#define HSI(ch, r, c) (((ch) * ITY + (r)) * STRIDE + (c))

// One 64x64 output tile per block.
// Stage A: horizontal 7-sums from registers (guarded float4 gmem loads) into
//          5 scalar SMEM planes. Stage B: lane owns an adjacent column PAIR;
//          ld.shared.b64 of a scalar plane = pre-packed f32x2 operand; vertical
//          running sums + SSIM formula all in packed fma.rn.f32x2.
__global__ __launch_bounds__(256, 2) void ssim_kernel(const float* __restrict__ X,
                                                      const float* __restrict__ Y,
                                                      float* __restrict__ out) {
    extern __shared__ float hs[];
    __shared__ float wsum[8];

    const int z = blockIdx.z;                 // b*3 + c
    const size_t base = (size_t)z * (HH * WW);
    const int x0 = blockIdx.x * TX;
    const int y0 = blockIdx.y * TY;
    const int tid = threadIdx.x, lane = tid & 31, warp = tid >> 5;

    // ---- stage A: horizontal 7-sums, 4 output cols per item ----
    for (int item = tid; item < ITY * (TX / 4); item += 256) {
        const int r = item >> 4;
        const int c0 = (item & 15) * 4;
        const int iy = y0 + r;
        const float* px = X + base + (size_t)iy * WW;
        const float* py = Y + base + (size_t)iy * WW;

        float ax[12], ay[12];
        #pragma unroll
        for (int k = 0; k < 3; k++) {
            const int col = x0 + c0 + 4 * k;
            const bool ok = (iy < HH) && (col <= WW - 4);  // col 16B-aligned
            float4 vx = ok ? *(const float4*)(px + col) : make_float4(0, 0, 0, 0);
            float4 vy = ok ? *(const float4*)(py + col) : make_float4(0, 0, 0, 0);
            ax[4 * k + 0] = vx.x; ax[4 * k + 1] = vx.y;
            ax[4 * k + 2] = vx.z; ax[4 * k + 3] = vx.w;
            ay[4 * k + 0] = vy.x; ay[4 * k + 1] = vy.y;
            ay[4 * k + 2] = vy.z; ay[4 * k + 3] = vy.w;
        }

        float s1 = 0.f, s2 = 0.f, s3 = 0.f, s4 = 0.f, s5 = 0.f;
        #pragma unroll
        for (int k = 0; k < 7; k++) {
            s1 += ax[k]; s2 += ay[k];
            s3 += ax[k] * ax[k]; s4 += ay[k] * ay[k]; s5 += ax[k] * ay[k];
        }
        hs[HSI(0, r, c0)] = s1; hs[HSI(1, r, c0)] = s2; hs[HSI(2, r, c0)] = s3;
        hs[HSI(3, r, c0)] = s4; hs[HSI(4, r, c0)] = s5;
        #pragma unroll
        for (int j = 1; j < 4; j++) {
            const float xn = ax[6 + j], yn = ay[6 + j];
            const float xo = ax[j - 1], yo = ay[j - 1];
            s1 += xn - xo;
            s2 += yn - yo;
            s3 += xn * xn - xo * xo;
            s4 += yn * yn - yo * yo;
            s5 += xn * yn - xo * yo;
            hs[HSI(0, r, c0 + j)] = s1; hs[HSI(1, r, c0 + j)] = s2;
            hs[HSI(2, r, c0 + j)] = s3; hs[HSI(3, r, c0 + j)] = s4;
            hs[HSI(4, r, c0 + j)] = s5;
        }
    }
    __syncthreads();

    // per-image constants
    const int b = z / CH;
    const float dr = __uint_as_float(g_maxBits[b]) - __uint_as_float(g_minBits[b]);
    const float c1 = (0.01f * dr) * (0.01f * dr);
    const float c2 = (0.03f * dr) * (0.03f * dr);
    const ull C1 = rep2(c1), C2 = rep2(c2);
    const ull INV = rep2(1.f / 49.f), COVN = rep2(49.f / 48.f);
    const ull M1 = rep2(-1.f), TWO = rep2(2.f);

    // ---- stage B: packed vertical running 7-sums + SSIM; 8 rows/thread ----
    const unsigned sb = (unsigned)__cvta_generic_to_shared(hs);
    const unsigned cb = sb + (unsigned)lane * 8u;   // column pair 2*lane
    const int r0 = warp * 8;
    const bool ok0 = (x0 + 2 * lane) < OW;
    const bool ok1 = (x0 + 2 * lane + 1) < OW;

    ull T1 = 0, T2 = 0, T3 = 0, T4 = 0, T5 = 0;
    #pragma unroll
    for (int k = 0; k < 7; k++) {
        const unsigned ra = cb + (unsigned)(r0 + k) * (STRIDE * 4);
        T1 = add2(T1, lds2(ra + 0 * (ITY * STRIDE * 4)));
        T2 = add2(T2, lds2(ra + 1 * (ITY * STRIDE * 4)));
        T3 = add2(T3, lds2(ra + 2 * (ITY * STRIDE * 4)));
        T4 = add2(T4, lds2(ra + 3 * (ITY * STRIDE * 4)));
        T5 = add2(T5, lds2(ra + 4 * (ITY * STRIDE * 4)));
    }

    float accS = 0.f;
    #pragma unroll
    for (int j = 0; j < 8; j++) {
        if (j > 0) {
            const unsigned rn = cb + (unsigned)(r0 + 6 + j) * (STRIDE * 4);
            const unsigned ro = cb + (unsigned)(r0 + j - 1) * (STRIDE * 4);
            T1 = add2(T1, lds2(rn + 0 * (ITY * STRIDE * 4)));
            T1 = fma2(lds2(ro + 0 * (ITY * STRIDE * 4)), M1, T1);
            T2 = add2(T2, lds2(rn + 1 * (ITY * STRIDE * 4)));
            T2 = fma2(lds2(ro + 1 * (ITY * STRIDE * 4)), M1, T2);
            T3 = add2(T3, lds2(rn + 2 * (ITY * STRIDE * 4)));
            T3 = fma2(lds2(ro + 2 * (ITY * STRIDE * 4)), M1, T3);
            T4 = add2(T4, lds2(rn + 3 * (ITY * STRIDE * 4)));
            T4 = fma2(lds2(ro + 3 * (ITY * STRIDE * 4)), M1, T4);
            T5 = add2(T5, lds2(rn + 4 * (ITY * STRIDE * 4)));
            T5 = fma2(lds2(ro + 4 * (ITY * STRIDE * 4)), M1, T5);
        }
        const int oy = y0 + r0 + j;                 // uniform across warp
        if (oy < OW) {
            ull UX = mul2(T1, INV), UY = mul2(T2, INV);
            ull UXX = mul2(T3, INV), UYY = mul2(T4, INV), UXY = mul2(T5, INV);
            ull UX2 = mul2(UX, UX), UY2 = mul2(UY, UY), UXUY = mul2(UX, UY);
            ull VX = mul2(fma2(UX2, M1, UXX), COVN);
            ull VY = mul2(fma2(UY2, M1, UYY), COVN);
            ull VXY = mul2(fma2(UXUY, M1, UXY), COVN);
            ull A1 = fma2(UXUY, TWO, C1);
            ull A2 = fma2(VXY, TWO, C2);
            ull B1 = add2(add2(UX2, UY2), C1);
            ull B2 = add2(add2(VX, VY), C2);
            ull NUM = mul2(A1, A2);
            ull DEN = mul2(B1, B2);
            float n0, n1, d0, d1;
            unpk(NUM, n0, n1);
            unpk(DEN, d0, d1);
            if (ok0) accS += __fdividef(n0, d0);
            if (ok1) accS += __fdividef(n1, d1);
        }
    }

    // ---- block reduction -> one double atomic; last block finalizes ----
    #pragma unroll
    for (int o = 16; o; o >>= 1) accS += __shfl_down_sync(F8, accS, o);
    if (lane == 0) wsum[warp] = accS;
    __syncthreads();
    if (tid == 0) {
        float s = 0.f;
        #pragma unroll
        for (int i = 0; i < 8; i++) s += wsum[i];
        atomicAdd(&g_acc, (double)s);
        __threadfence();
        unsigned t = atomicAdd(&g_done, 1u);
        if (t == NBLOCKS - 1) {
            out[0] = (float)(1.0 - g_acc / ((double)BATCH * CH * OW * OW));
            g_acc = 0.0;
            g_done = 0u;
            #pragma unroll
            for (int i = 0; i < BATCH; i++) { g_minBits[i] = F8; g_maxBits[i] = 0u; }
        }
    }
}

extern "C" void kernel_launch(void* const* d_in, const int* in_sizes, int n_in,
                              void* d_out, int out_size) {
    const float* img1 = (const float*)d_in[0];
    const float* img2 = (const float*)d_in[1];

    const int smem_bytes = 5 * ITY * STRIDE * (int)sizeof(float);  // 100,800 B
    cudaFuncSetAttribute(ssim_kernel, cudaFuncAttributeMaxDynamicSharedMemorySize,
                         smem_bytes);

    minmax_kernel<<<dim3(BATCH, 32), 256>>>(img2);
    dim3 grid((OW + TX - 1) / TX, (OW + TY - 1) / TY, BATCH * CH);  // 8,8,96
    ssim_kernel<<<grid, 256, smem_bytes>>>(img1, img2, (float*)d_out);
}

// round 5
// speedup vs baseline: 1.1749x; 1.1749x over previous
#include <cuda_runtime.h>

#define HH 512
#define WW 512
#define OW 506
#define BATCH 32
#define CH 3
#define TX 64
#define TY 32
#define ITY 38          // TY + 6
#define STRIDE 66       // floats per hs row (even -> 8B-aligned LDS.64)
#define GX 8            // ceil(506/64)
#define GY 16           // ceil(506/32)
#define NBLOCKS (GX * GY * BATCH * CH)
#define PLANE (ITY * STRIDE)

#define F8 0xFFFFFFFFu
__device__ unsigned g_minBits[BATCH] = {
    F8, F8, F8, F8, F8, F8, F8, F8, F8, F8, F8, F8, F8, F8, F8, F8,
    F8, F8, F8, F8, F8, F8, F8, F8, F8, F8, F8, F8, F8, F8, F8, F8};
__device__ unsigned g_maxBits[BATCH];  // zero-init at load
__device__ double g_acc;               // zero-init at load
__device__ unsigned g_done;            // zero-init at load

// ---------------- packed f32x2 helpers ----------------
typedef unsigned long long ull;
__device__ __forceinline__ ull rep2(float f) {
    ull r; asm("mov.b64 %0,{%1,%1};" : "=l"(r) : "f"(f)); return r;
}
__device__ __forceinline__ ull add2(ull a, ull b) {
    ull d; asm("add.rn.f32x2 %0,%1,%2;" : "=l"(d) : "l"(a), "l"(b)); return d;
}
__device__ __forceinline__ ull mul2(ull a, ull b) {
    ull d; asm("mul.rn.f32x2 %0,%1,%2;" : "=l"(d) : "l"(a), "l"(b)); return d;
}
__device__ __forceinline__ ull fma2(ull a, ull b, ull c) {
    ull d; asm("fma.rn.f32x2 %0,%1,%2,%3;" : "=l"(d) : "l"(a), "l"(b), "l"(c)); return d;
}
__device__ __forceinline__ void unpk(ull v, float& a, float& b) {
    asm("mov.b64 {%0,%1},%2;" : "=f"(a), "=f"(b) : "l"(v));
}
__device__ __forceinline__ ull lds2(unsigned a) {
    ull v; asm volatile("ld.shared.b64 %0,[%1];" : "=l"(v) : "r"(a)); return v;
}

// Per-image min/max of img2 (values >= 0 -> uint ordering == float ordering).
__global__ void minmax_kernel(const float* __restrict__ img2) {
    int b = blockIdx.x;
    const float4* p = (const float4*)(img2 + (size_t)b * (CH * HH * WW));
    const int n4 = CH * HH * WW / 4;           // 196608
    const int stride = gridDim.y * blockDim.x; // 8192
    unsigned lo = F8, hi = 0u;
    int i = blockIdx.y * blockDim.x + threadIdx.x;
    for (; i + 3 * stride < n4; i += 4 * stride) {
        float4 v0 = p[i];
        float4 v1 = p[i + stride];
        float4 v2 = p[i + 2 * stride];
        float4 v3 = p[i + 3 * stride];
        #define MM(v) { \
            unsigned a0 = __float_as_uint((v).x), a1 = __float_as_uint((v).y); \
            unsigned a2 = __float_as_uint((v).z), a3 = __float_as_uint((v).w); \
            lo = min(lo, min(min(a0, a1), min(a2, a3))); \
            hi = max(hi, max(max(a0, a1), max(a2, a3))); }
        MM(v0) MM(v1) MM(v2) MM(v3)
    }
    for (; i < n4; i += stride) { float4 v = p[i]; MM(v) }
    #undef MM
    #pragma unroll
    for (int o = 16; o; o >>= 1) {
        lo = min(lo, __shfl_down_sync(F8, lo, o));
        hi = max(hi, __shfl_down_sync(F8, hi, o));
    }
    __shared__ unsigned slo[8], shi[8];
    int lane = threadIdx.x & 31, w = threadIdx.x >> 5;
    if (lane == 0) { slo[w] = lo; shi[w] = hi; }
    __syncthreads();
    if (threadIdx.x == 0) {
        #pragma unroll
        for (int k = 1; k < 8; k++) { lo = min(lo, slo[k]); hi = max(hi, shi[k]); }
        atomicMin(&g_minBits[b], lo);
        atomicMax(&g_maxBits[b], hi);
    }
}

#define HSI(ch, r, c) (((ch) * ITY + (r)) * STRIDE + (c))

// One 64x32 output tile per block. 4 SMEM planes: sum(x), sum(y),
// sum(x^2+y^2), sum(xy). Stage A: horizontal 7-sums from registers.
// Stage B: lane owns adjacent column pair; packed f32x2 vertical running
// sums + SSIM. 4 blocks/SM (regs capped at 64).
__global__ __launch_bounds__(256, 4) void ssim_kernel(const float* __restrict__ X,
                                                      const float* __restrict__ Y,
                                                      float* __restrict__ out) {
    extern __shared__ float hs[];
    __shared__ float wsum[8];

    const int z = blockIdx.z;                 // b*3 + c
    const size_t base = (size_t)z * (HH * WW);
    const int x0 = blockIdx.x * TX;
    const int y0 = blockIdx.y * TY;
    const int tid = threadIdx.x, lane = tid & 31, warp = tid >> 5;

    // ---- stage A: horizontal 7-sums, 4 output cols per item ----
    for (int item = tid; item < ITY * (TX / 4); item += 256) {
        const int r = item >> 4;
        const int c0 = (item & 15) * 4;
        const int iy = y0 + r;
        const float* px = X + base + (size_t)iy * WW;
        const float* py = Y + base + (size_t)iy * WW;

        float ax[12], ay[12];
        #pragma unroll
        for (int k = 0; k < 3; k++) {
            const int col = x0 + c0 + 4 * k;
            const bool ok = (iy < HH) && (col <= WW - 4);  // col 16B-aligned
            float4 vx = ok ? *(const float4*)(px + col) : make_float4(0, 0, 0, 0);
            float4 vy = ok ? *(const float4*)(py + col) : make_float4(0, 0, 0, 0);
            ax[4 * k + 0] = vx.x; ax[4 * k + 1] = vx.y;
            ax[4 * k + 2] = vx.z; ax[4 * k + 3] = vx.w;
            ay[4 * k + 0] = vy.x; ay[4 * k + 1] = vy.y;
            ay[4 * k + 2] = vy.z; ay[4 * k + 3] = vy.w;
        }

        float s1 = 0.f, s2 = 0.f, s34 = 0.f, s5 = 0.f;
        #pragma unroll
        for (int k = 0; k < 7; k++) {
            s1 += ax[k]; s2 += ay[k];
            s34 += ax[k] * ax[k] + ay[k] * ay[k];
            s5 += ax[k] * ay[k];
        }
        hs[HSI(0, r, c0)] = s1; hs[HSI(1, r, c0)] = s2;
        hs[HSI(2, r, c0)] = s34; hs[HSI(3, r, c0)] = s5;
        #pragma unroll
        for (int j = 1; j < 4; j++) {
            const float xn = ax[6 + j], yn = ay[6 + j];
            const float xo = ax[j - 1], yo = ay[j - 1];
            s1 += xn - xo;
            s2 += yn - yo;
            s34 += xn * xn + yn * yn - xo * xo - yo * yo;
            s5 += xn * yn - xo * yo;
            hs[HSI(0, r, c0 + j)] = s1; hs[HSI(1, r, c0 + j)] = s2;
            hs[HSI(2, r, c0 + j)] = s34; hs[HSI(3, r, c0 + j)] = s5;
        }
    }
    __syncthreads();

    // per-image constants
    const int b = z / CH;
    const float dr = __uint_as_float(g_maxBits[b]) - __uint_as_float(g_minBits[b]);
    const float c1 = (0.01f * dr) * (0.01f * dr);
    const float c2 = (0.03f * dr) * (0.03f * dr);
    const ull C1 = rep2(c1), C2 = rep2(c2);
    const ull INV = rep2(1.f / 49.f), COVN = rep2(49.f / 48.f);
    const ull M1 = rep2(-1.f), TWO = rep2(2.f);

    // ---- stage B: packed vertical running 7-sums + SSIM; 4 rows/thread ----
    const unsigned sb = (unsigned)__cvta_generic_to_shared(hs);
    const unsigned cb = sb + (unsigned)lane * 8u;   // column pair 2*lane
    const int r0 = warp * 4;
    const bool ok0 = (x0 + 2 * lane) < OW;
    const bool ok1 = (x0 + 2 * lane + 1) < OW;

    ull T1 = 0, T2 = 0, T34 = 0, T5 = 0;
    #pragma unroll
    for (int k = 0; k < 7; k++) {
        const unsigned ra = cb + (unsigned)(r0 + k) * (STRIDE * 4);
        T1 = add2(T1, lds2(ra + 0 * (PLANE * 4)));
        T2 = add2(T2, lds2(ra + 1 * (PLANE * 4)));
        T34 = add2(T34, lds2(ra + 2 * (PLANE * 4)));
        T5 = add2(T5, lds2(ra + 3 * (PLANE * 4)));
    }

    float accS = 0.f;
    #pragma unroll
    for (int j = 0; j < 4; j++) {
        if (j > 0) {
            const unsigned rn = cb + (unsigned)(r0 + 6 + j) * (STRIDE * 4);
            const unsigned ro = cb + (unsigned)(r0 + j - 1) * (STRIDE * 4);
            T1 = add2(T1, lds2(rn + 0 * (PLANE * 4)));
            T1 = fma2(lds2(ro + 0 * (PLANE * 4)), M1, T1);
            T2 = add2(T2, lds2(rn + 1 * (PLANE * 4)));
            T2 = fma2(lds2(ro + 1 * (PLANE * 4)), M1, T2);
            T34 = add2(T34, lds2(rn + 2 * (PLANE * 4)));
            T34 = fma2(lds2(ro + 2 * (PLANE * 4)), M1, T34);
            T5 = add2(T5, lds2(rn + 3 * (PLANE * 4)));
            T5 = fma2(lds2(ro + 3 * (PLANE * 4)), M1, T5);
        }
        const int oy = y0 + r0 + j;                 // uniform across warp
        if (oy < OW) {
            ull UX = mul2(T1, INV), UY = mul2(T2, INV);
            ull U34 = mul2(T34, INV), UXY = mul2(T5, INV);
            ull UX2 = mul2(UX, UX), UY2 = mul2(UY, UY), UXUY = mul2(UX, UY);
            ull SUMU2 = add2(UX2, UY2);
            ull VXY = mul2(fma2(UXUY, M1, UXY), COVN);
            ull VSUM = mul2(fma2(SUMU2, M1, U34), COVN);
            ull A1 = fma2(UXUY, TWO, C1);
            ull A2 = fma2(VXY, TWO, C2);
            ull B1 = add2(SUMU2, C1);
            ull B2 = add2(VSUM, C2);
            ull NUM = mul2(A1, A2);
            ull DEN = mul2(B1, B2);
            float n0, n1, d0, d1;
            unpk(NUM, n0, n1);
            unpk(DEN, d0, d1);
            if (ok0) accS += __fdividef(n0, d0);
            if (ok1) accS += __fdividef(n1, d1);
        }
    }

    // ---- block reduction -> one double atomic; last block finalizes ----
    #pragma unroll
    for (int o = 16; o; o >>= 1) accS += __shfl_down_sync(F8, accS, o);
    if (lane == 0) wsum[warp] = accS;
    __syncthreads();
    if (tid == 0) {
        float s = 0.f;
        #pragma unroll
        for (int i = 0; i < 8; i++) s += wsum[i];
        atomicAdd(&g_acc, (double)s);
        __threadfence();
        unsigned t = atomicAdd(&g_done, 1u);
        if (t == NBLOCKS - 1) {
            out[0] = (float)(1.0 - g_acc / ((double)BATCH * CH * OW * OW));
            g_acc = 0.0;
            g_done = 0u;
            #pragma unroll
            for (int i = 0; i < BATCH; i++) { g_minBits[i] = F8; g_maxBits[i] = 0u; }
        }
    }
}

extern "C" void kernel_launch(void* const* d_in, const int* in_sizes, int n_in,
                              void* d_out, int out_size) {
    const float* img1 = (const float*)d_in[0];
    const float* img2 = (const float*)d_in[1];

    const int smem_bytes = 4 * PLANE * (int)sizeof(float);  // 40,128 B
    cudaFuncSetAttribute(ssim_kernel, cudaFuncAttributeMaxDynamicSharedMemorySize,
                         smem_bytes);

    minmax_kernel<<<dim3(BATCH, 32), 256>>>(img2);
    dim3 grid(GX, GY, BATCH * CH);  // 8,16,96
    ssim_kernel<<<grid, 256, smem_bytes>>>(img1, img2, (float*)d_out);
}